// round 16
// baseline (speedup 1.0000x reference)
#include <cuda_runtime.h>

#define Z 64      // z_dim
#define H 256     // hidden
#define C 5       // num classes
#define GMAX 16
#define MAXBLK 64
#define T1 64     // phase-1 tile rows (async pipeline granularity)
#define T3 96     // phase-3 tile rows
#define TILE_F4 (T1 * 16)        // float4 entries per phase-1 tile (1024)

// partial class sums: layout [g][c][blk][d]
__device__ __align__(16) float g_part[GMAX * C * MAXBLK * Z];
__device__ int      g_cntp[GMAX * MAXBLK * C];   // per (g, block) class counts
__device__ __align__(16) float g_D[GMAX * C * Z];
__device__ unsigned          g_t1[GMAX];          // phase-1 tile queue
__device__ unsigned          g_t3[GMAX];          // phase-3 tile queue (reverse)
__device__ unsigned          g_arrive[GMAX];
__device__ volatile unsigned g_ready[GMAX];
__device__ unsigned          g_done[GMAX];

__device__ __forceinline__ void acc_add(float4& a, const float4& v) {
    a.x += v.x; a.y += v.y; a.z += v.z; a.w += v.w;
}
__device__ __forceinline__ unsigned smem_u32(const void* p) {
    return (unsigned)__cvta_generic_to_shared(p);
}
__device__ __forceinline__ void cp16(unsigned s, const void* gp) {
    asm volatile("cp.async.cg.shared.global [%0], [%1], 16;" :: "r"(s), "l"(gp));
}
__device__ __forceinline__ void cp_commit() { asm volatile("cp.async.commit_group;"); }
__device__ __forceinline__ void cp_wait1()  { asm volatile("cp.async.wait_group 1;" ::: "memory"); }
__device__ __forceinline__ void cp_wait0()  { asm volatile("cp.async.wait_group 0;" ::: "memory"); }

// Persistent fused kernel; per-graph decoupled sync; R9 claim-ahead stealing.
// Phase 1 streams x through a cp.async double-buffered smem pipeline so DRAM
// delivery is decoupled from warp consumption (LDGSTS has no depth cap).
// Grid (nblk, G), single wave (nblk*G <= 592 @ 4/SM — required for the spin
// loops to be deadlock-free).
__global__ void __launch_bounds__(256, 4)
fused_kernel(const float* __restrict__ x,
             const int*   __restrict__ label,
             const float* __restrict__ W1,
             const float* __restrict__ b1,
             const float* __restrict__ W2,
             const float* __restrict__ b2,
             float*       __restrict__ out,
             int N, int nblk, int nt1, int nt3) {
    int g    = blockIdx.y;
    int bx   = blockIdx.x;
    int tid  = threadIdx.x;
    int lane = tid & 15;   // float4 index within 64-dim row
    int grp  = tid >> 4;   // 16 row-groups

    __shared__ float4 buf[2][TILE_F4];     // 32 KB double buffer
    __shared__ float  s_mid[Z];
    __shared__ float  h_mid[H];
    __shared__ float  part[4][Z];
    __shared__ int    scnt[C];
    __shared__ int    s_tile[2];
    __shared__ float4 sD[C * 16];

    const char* xg = (const char*)(x + (size_t)g * N * Z);
    const size_t nf4 = (size_t)N * 16;     // total float4 entries in this graph

    // ================= phase 1: cp.async pipelined class sums =============
    float4 acc[C];
    int    cnt[C];
#pragma unroll
    for (int c = 0; c < C; c++) { acc[c] = make_float4(0.f, 0.f, 0.f, 0.f); cnt[c] = 0; }

#define FILL(tt, bb) do {                                                     \
        size_t _be = (size_t)(tt) * TILE_F4;                                  \
        unsigned _sb = smem_u32(&buf[(bb)][0]);                               \
        _Pragma("unroll")                                                     \
        for (int _k = 0; _k < 4; _k++) {                                      \
            int _e = tid + 256 * _k;                                          \
            if (_be + _e < nf4)                                               \
                cp16(_sb + _e * 16, xg + (_be + _e) * 16);                    \
        }                                                                     \
        cp_commit();                                                          \
    } while (0)

    // prologue: claim + fill both buffers
    if (tid == 0) s_tile[0] = (int)atomicAdd(&g_t1[g], 1u);
    __syncthreads();
    int tcur = s_tile[0];
    FILL(tcur, 0);
    if (tid == 0) s_tile[1] = (int)atomicAdd(&g_t1[g], 1u);
    __syncthreads();
    int toth = s_tile[1];
    FILL(toth, 1);

    int p = 0;
    while (tcur < nt1) {
        // claim two-ahead (hidden behind wait + process)
        if (tid == 0) s_tile[p] = (int)atomicAdd(&g_t1[g], 1u);
        cp_wait1();                       // buf[p] (oldest group) complete
        __syncthreads();                  // fills + s_tile[p] visible block-wide

        // process tile tcur from buf[p]: 16 groups x 4 rows
        {
            int base = tcur * T1;
            int n0 = base + grp;
            int n1 = n0 + 16, n2 = n0 + 32, n3 = n0 + 48;
            bool f0 = n0 < N, f1 = n1 < N, f2 = n2 < N, f3 = n3 < N;
            int    c0 = f0 ? __ldg(label + n0) : -1;
            int    c1 = f1 ? __ldg(label + n1) : -1;
            int    c2 = f2 ? __ldg(label + n2) : -1;
            int    c3 = f3 ? __ldg(label + n3) : -1;
            float4 v0 = buf[p][grp * 16 + lane];
            float4 v1 = buf[p][(grp + 16) * 16 + lane];
            float4 v2 = buf[p][(grp + 32) * 16 + lane];
            float4 v3 = buf[p][(grp + 48) * 16 + lane];
#pragma unroll
            for (int cc = 0; cc < C; cc++) {
                if (c0 == cc) acc_add(acc[cc], v0);
                if (c1 == cc) acc_add(acc[cc], v1);
                if (c2 == cc) acc_add(acc[cc], v2);
                if (c3 == cc) acc_add(acc[cc], v3);
                cnt[cc] += (c0 == cc) + (c1 == cc) + (c2 == cc) + (c3 == cc);
            }
        }
        int tnew = s_tile[p];
        __syncthreads();                  // everyone done reading buf[p]
        FILL(tnew, p);                    // refill (empty group if tnew>=nt1)
        tcur = toth; toth = tnew; p ^= 1;
    }
    cp_wait0();
    __syncthreads();

    // flush: counts + partial sums into this block's static slot bx.
    // sacc aliases buf[0..] (20 KB <= 32 KB), safe after the pipeline drained.
    {
        float4 (*sacc)[C][16] = reinterpret_cast<float4(*)[C][16]>(&buf[0][0]);
        if (tid < C) scnt[tid] = 0;
#pragma unroll
        for (int c = 0; c < C; c++) sacc[grp][c][lane] = acc[c];
        __syncthreads();
        if (lane == 0) {
#pragma unroll
            for (int c = 0; c < C; c++)
                if (cnt[c]) atomicAdd(&scnt[c], cnt[c]);
        }
        __syncthreads();
        if (tid < C) g_cntp[(g * nblk + bx) * C + tid] = scnt[tid];
        if (tid < C * 16) {
            int c = tid >> 4, d4 = tid & 15;
            float4 s = sacc[0][c][d4];
#pragma unroll
            for (int g2 = 1; g2 < 16; g2++) {
                float4 t2 = sacc[g2][c][d4];
                s.x += t2.x; s.y += t2.y; s.z += t2.z; s.w += t2.w;
            }
            float4* P4 = reinterpret_cast<float4*>(g_part);
            P4[((size_t)(g * C + c) * nblk + bx) * 16 + d4] = s;
        }
    }
    __syncthreads();
    if (tid == 0) {
        __threadfence();
        atomicAdd(&g_arrive[g], 1u);
    }
    __syncthreads();

    // ================= phase 2: parallel mid GEMM (blocks bx < C) =========
    if (bx < C) {
        int c = bx;
        int r = g * C + c;

        if (tid == 0) {
            while (*(volatile unsigned*)&g_arrive[g] < (unsigned)nblk)
                __nanosleep(64);
            __threadfence();   // acquire partials
        }
        __syncthreads();

        // total class count for (g, c)
        if (tid < 32) {
            int sum = 0;
            for (int b = tid; b < nblk; b += 32)
                sum += g_cntp[(g * nblk + b) * C + c];
#pragma unroll
            for (int o = 16; o > 0; o >>= 1)
                sum += __shfl_down_sync(0xffffffffu, sum, o);
            if (tid == 0) scnt[0] = max(sum, 1);
        }

        // sum partials
        const float* P = g_part + (size_t)r * nblk * Z;
        int d = tid & 63, j = tid >> 6;
        float p0 = 0.f, p1 = 0.f;
        int b = j;
        for (; b + 4 < nblk; b += 8) {
            p0 += P[b * Z + d];
            p1 += P[(b + 4) * Z + d];
        }
        if (b < nblk) p0 += P[b * Z + d];
        part[j][d] = p0 + p1;
        __syncthreads();

        float inv = 1.f / (float)scnt[0];
        if (tid < Z)
            s_mid[tid] = (part[0][tid] + part[1][tid]
                        + part[2][tid] + part[3][tid]) * inv;
        __syncthreads();

        // layer 1
        float accv = __ldg(b1 + tid);
#pragma unroll
        for (int dd = 0; dd < Z; dd++)
            accv = fmaf(s_mid[dd], __ldg(W1 + dd * H + tid), accv);
        h_mid[tid] = fmaxf(accv, 0.f);
        __syncthreads();

        // layer 2
        int lane2 = tid & 63, grp2 = tid >> 6;
        float p2 = 0.f;
#pragma unroll
        for (int jj = 0; jj < 64; jj++) {
            int jidx = grp2 * 64 + jj;
            p2 = fmaf(h_mid[jidx], __ldg(W2 + jidx * Z + lane2), p2);
        }
        __syncthreads();
        part[grp2][lane2] = p2;
        __syncthreads();
        if (tid < Z)
            g_D[r * Z + tid] = __ldg(b2 + tid) + part[0][tid] + part[1][tid]
                             + part[2][tid] + part[3][tid];
        __syncthreads();

        if (tid == 0) {
            __threadfence();
            atomicAdd((unsigned*)&g_ready[g], 1u);
        }
    }

    // ================= wait for this graph's D ============================
    if (tid == 0) {
        while (g_ready[g] < (unsigned)C) __nanosleep(64);
        __threadfence();   // acquire g_D[g]
    }
    __syncthreads();

    if (tid < C * 16)
        sD[tid] = reinterpret_cast<const float4*>(g_D)[g * C * 16 + tid];
    __syncthreads();

    // ================= phase 3: out = x + D[label], stolen reverse tiles ==
    {
        const float4* x4 = reinterpret_cast<const float4*>(x);
        float4*       o4 = reinterpret_cast<float4*>(out);

        if (tid == 0) s_tile[0] = (int)atomicAdd(&g_t3[g], 1u);
        __syncthreads();
        for (;;) {
            int t = s_tile[0];
            if (t >= nt3) break;
            __syncthreads();
            if (tid == 0) s_tile[0] = (int)atomicAdd(&g_t3[g], 1u);

            // reverse sweep: tile t covers rows [N-(t+1)*T3, N-t*T3)
            int hi = N - t * T3;
            int lo = hi - T3; if (lo < 0) lo = 0;

            if (hi - lo == T3) {
                int n = lo + grp;
                int c0 = __ldg(label + n);
                int c1 = __ldg(label + n + 16);
                int c2 = __ldg(label + n + 32);
                int c3 = __ldg(label + n + 48);
                int c4 = __ldg(label + n + 64);
                int c5 = __ldg(label + n + 80);
                size_t i0 = ((size_t)g * N + n) * 16 + lane;
                float4 v0 = __ldg(x4 + i0);
                float4 v1 = __ldg(x4 + i0 + 16 * 16);
                float4 v2 = __ldg(x4 + i0 + 32 * 16);
                float4 v3 = __ldg(x4 + i0 + 48 * 16);
                float4 v4 = __ldg(x4 + i0 + 64 * 16);
                float4 v5 = __ldg(x4 + i0 + 80 * 16);
                float4 d0 = sD[c0 * 16 + lane];
                float4 d1 = sD[c1 * 16 + lane];
                float4 d2 = sD[c2 * 16 + lane];
                float4 d3 = sD[c3 * 16 + lane];
                float4 d4 = sD[c4 * 16 + lane];
                float4 d5 = sD[c5 * 16 + lane];
                v0.x += d0.x; v0.y += d0.y; v0.z += d0.z; v0.w += d0.w;
                v1.x += d1.x; v1.y += d1.y; v1.z += d1.z; v1.w += d1.w;
                v2.x += d2.x; v2.y += d2.y; v2.z += d2.z; v2.w += d2.w;
                v3.x += d3.x; v3.y += d3.y; v3.z += d3.z; v3.w += d3.w;
                v4.x += d4.x; v4.y += d4.y; v4.z += d4.z; v4.w += d4.w;
                v5.x += d5.x; v5.y += d5.y; v5.z += d5.z; v5.w += d5.w;
                __stcs(o4 + i0,           v0);
                __stcs(o4 + i0 + 16 * 16, v1);
                __stcs(o4 + i0 + 32 * 16, v2);
                __stcs(o4 + i0 + 48 * 16, v3);
                __stcs(o4 + i0 + 64 * 16, v4);
                __stcs(o4 + i0 + 80 * 16, v5);
            } else {
                for (int n = lo + grp; n < hi; n += 16) {
                    int    c   = __ldg(label + n);
                    size_t idx = ((size_t)g * N + n) * 16 + lane;
                    float4 xv  = __ldg(x4 + idx);
                    float4 dv  = sD[c * 16 + lane];
                    xv.x += dv.x; xv.y += dv.y; xv.z += dv.z; xv.w += dv.w;
                    __stcs(o4 + idx, xv);
                }
            }
            __syncthreads();
        }
    }

    // ================= self-reset for graph replay ========================
    __syncthreads();
    if (tid == 0) {
        __threadfence();
        unsigned prev = atomicAdd(&g_done[g], 1u);
        if (prev == (unsigned)(nblk - 1)) {
            g_t1[g]     = 0u;
            g_t3[g]     = 0u;
            g_arrive[g] = 0u;
            g_ready[g]  = 0u;
            g_done[g]   = 0u;
            __threadfence();
        }
    }
}

// ---------------------------------------------------------------- launcher
extern "C" void kernel_launch(void* const* d_in, const int* in_sizes, int n_in,
                              void* d_out, int out_size) {
    const float* x     = (const float*)d_in[0];
    const int*   label = (const int*)  d_in[1];
    const float* W1    = (const float*)d_in[2];
    const float* b1    = (const float*)d_in[3];
    const float* W2    = (const float*)d_in[4];
    const float* b2    = (const float*)d_in[5];
    float*       out   = (float*)d_out;

    int N = in_sizes[1];                 // 40000
    int G = in_sizes[0] / (N * Z);       // 16

    // Single wave: blocks = G * nblk <= 576 (< 592 slots @ 4/SM).
    int nblk = 576 / G;                  // 36 for G=16
    if (nblk > MAXBLK) nblk = MAXBLK;
    if (nblk < C + 1) nblk = C + 1;      // need >= C blocks per graph for mid

    int nt1 = (N + T1 - 1) / T1;
    int nt3 = (N + T3 - 1) / T3;

    dim3 grid(nblk, G);
    fused_kernel<<<grid, 256>>>(x, label, W1, b1, W2, b2, out,
                                N, nblk, nt1, nt3);
}